// round 7
// baseline (speedup 1.0000x reference)
#include <cuda_runtime.h>
#include <cstdint>

#define BATCH 8
#define H 256
#define W 256
#define NTOT (BATCH * H * W)
#define INF_VAL 1e10f

// Scratch (no allocations allowed): tmp after pass1, d2 after pass2.
__device__ float g_tmp[NTOT];
__device__ float g_d2[NTOT];
__device__ unsigned int g_maxbits;

// ---------------------------------------------------------------------------
// Pass 1 (x-direction). Because the source costs are binary {0, INF}, the
// min-plus convolution reduces to (distance to nearest fg pixel in the row)^2.
// Computed exactly with two Hillis-Steele scans (nearest fg index left/right).
// One block per (b, y) row, 256 threads. Block 0 also resets the global max
// (safe: g_maxbits is next touched by pass2, which is ordered after all of
// pass1 by the kernel boundary).
// ---------------------------------------------------------------------------
__global__ void pass1_kernel(const float* __restrict__ mask) {
    const int row = blockIdx.x;           // b*H + y
    const int x = threadIdx.x;

    if (row == 0 && x == 0) g_maxbits = 0u;

    __shared__ int sL[W];
    __shared__ int sR[W];

    const float mv = mask[row * W + x];
    const bool fg = (mv > 0.5f);
    sL[x] = fg ? x : -1;                  // largest fg index <= x
    sR[x] = fg ? x : W;                   // smallest fg index >= x
    __syncthreads();

    #pragma unroll
    for (int d = 1; d < W; d <<= 1) {
        const int vl = (x >= d)     ? sL[x - d] : -1;
        const int vr = (x + d < W)  ? sR[x + d] : W;
        __syncthreads();
        if (vl > sL[x]) sL[x] = vl;
        if (vr < sR[x]) sR[x] = vr;
        __syncthreads();
    }

    const int L = sL[x];
    const int R = sR[x];
    float best = INF_VAL;                 // matches reference: min at xq==x gives INF+0
    if (L >= 0) { const int dl = x - L; best = fminf(best, (float)(dl * dl)); }
    if (R < W)  { const int dr = R - x; best = fminf(best, (float)(dr * dr)); }
    g_tmp[row * W + x] = best;
}

// ---------------------------------------------------------------------------
// Pass 2 (y-direction): d2[b,yi,x] = min_yq ( (yi-yq)^2 + tmp[b,yq,x] ).
// Block = (32 x-columns) x (64 yi rows); grid (W/32, H/64, B).
// Full column (256 yq) of 32 x-lanes staged in shared (32 KB, conflict-free:
// address = yq*32 + tx -> bank = tx). Each thread owns 8 yi accumulators so
// one LDS feeds 8 FMA+FMIN pairs. Per-warp max folded into one atomicMax.
// ---------------------------------------------------------------------------
__global__ void __launch_bounds__(256) pass2_kernel(const float* __restrict__ tmp,
                                                    float* __restrict__ d2out) {
    const int b  = blockIdx.z;
    const int xt = blockIdx.x;            // 0..7  (x tile of 32)
    const int yc = blockIdx.y;            // 0..3  (yi chunk of 64)
    const int tx = threadIdx.x;           // 0..31
    const int ty = threadIdx.y;           // 0..7

    __shared__ float sh[H][32];

    const float* base = tmp + b * H * W + xt * 32;
    #pragma unroll
    for (int i = 0; i < H / 8; i++) {
        const int y = ty + i * 8;
        sh[y][tx] = base[y * W + tx];     // 128B coalesced per warp
    }
    __syncthreads();

    const int yi0 = yc * 64 + ty;         // thread's yi set: yi0 + 8k, k=0..7
    float best[8];
    float dy[8];
    #pragma unroll
    for (int k = 0; k < 8; k++) {
        best[k] = 3e38f;
        dy[k] = (float)(yi0 + 8 * k);     // yi - yq, decremented as yq advances
    }

    #pragma unroll 4
    for (int yq = 0; yq < H; yq++) {
        const float s = sh[yq][tx];
        #pragma unroll
        for (int k = 0; k < 8; k++) {
            best[k] = fminf(best[k], fmaf(dy[k], dy[k], s));
            dy[k] -= 1.0f;
        }
    }

    float lmax = 0.0f;
    float* out = d2out + b * H * W + xt * 32 + tx;
    #pragma unroll
    for (int k = 0; k < 8; k++) {
        const int yi = yi0 + 8 * k;
        out[yi * W] = best[k];
        lmax = fmaxf(lmax, best[k]);
    }

    // warp max (lanes = tx across a fixed ty), one atomic per warp
    #pragma unroll
    for (int off = 16; off; off >>= 1)
        lmax = fmaxf(lmax, __shfl_xor_sync(0xFFFFFFFFu, lmax, off));
    if (tx == 0)
        atomicMax(&g_maxbits, __float_as_uint(lmax));   // valid: all >= 0
}

// ---------------------------------------------------------------------------
// Finalize: out = 2 * sigmoid(-sqrt(d2) * 50 / (sqrt(max d2) + 1))
//             = 2 / (1 + exp(sqrt(d2) * 50 / (maxd + 1)))
// ---------------------------------------------------------------------------
__global__ void finalize_kernel(const float* __restrict__ d2,
                                float* __restrict__ out, int n) {
    const int i = blockIdx.x * blockDim.x + threadIdx.x;
    if (i >= n) return;
    const float maxd = sqrtf(__uint_as_float(g_maxbits)) + 1.0f;
    const float scale = 50.0f / maxd;
    const float z = sqrtf(d2[i]) * scale;
    out[i] = 2.0f / (1.0f + expf(z));
}

// ---------------------------------------------------------------------------
extern "C" void kernel_launch(void* const* d_in, const int* in_sizes, int n_in,
                              void* d_out, int out_size) {
    const float* mask = (const float*)d_in[0];
    float* out = (float*)d_out;

    float* tmp_ptr;
    float* d2_ptr;
    cudaGetSymbolAddress((void**)&tmp_ptr, g_tmp);
    cudaGetSymbolAddress((void**)&d2_ptr, g_d2);

    pass1_kernel<<<BATCH * H, W>>>(mask);
    {
        dim3 grid(W / 32, H / 64, BATCH);
        dim3 block(32, 8);
        pass2_kernel<<<grid, block>>>(tmp_ptr, d2_ptr);
    }
    finalize_kernel<<<(NTOT + 255) / 256, 256>>>(d2_ptr, out, NTOT);
}

// round 9
// speedup vs baseline: 1.2140x; 1.2140x over previous
#include <cuda_runtime.h>
#include <cstdint>

#define BATCH 8
#define H 256
#define W 256
#define NTOT (BATCH * H * W)
#define INF_VAL 1e10f

__device__ float g_tmp[NTOT];
__device__ float g_d2[NTOT];
__device__ unsigned int g_maxbits;

// ---- packed f32x2 helpers (Blackwell; FFMA2 only reachable via PTX) --------
__device__ __forceinline__ unsigned long long pack2(float lo, float hi) {
    unsigned long long r;
    asm("mov.b64 %0, {%1, %2};" : "=l"(r) : "r"(__float_as_uint(lo)), "r"(__float_as_uint(hi)));
    return r;
}
__device__ __forceinline__ void unpack2(unsigned long long v, float& lo, float& hi) {
    unsigned int a, b;
    asm("mov.b64 {%0, %1}, %2;" : "=r"(a), "=r"(b) : "l"(v));
    lo = __uint_as_float(a); hi = __uint_as_float(b);
}
__device__ __forceinline__ unsigned long long fma2(unsigned long long a,
                                                   unsigned long long b,
                                                   unsigned long long c) {
    unsigned long long r;
    asm("fma.rn.f32x2 %0, %1, %2, %3;" : "=l"(r) : "l"(a), "l"(b), "l"(c));
    return r;
}
__device__ __forceinline__ unsigned long long add2(unsigned long long a,
                                                   unsigned long long b) {
    unsigned long long r;
    asm("add.rn.f32x2 %0, %1, %2;" : "=l"(r) : "l"(a), "l"(b));
    return r;
}

// ---------------------------------------------------------------------------
// Pass 1 (x-direction), barrier-free. One warp per row. 8 ballots build the
// row's 256-bit foreground bitmap in registers (ballot is warp-uniform), then
// each lane resolves nearest-set-bit left/right for its 8 pixels via clz/ffs.
// Replaces the 16-__syncthreads Hillis-Steele scan (measured 7.97us,
// barrier-serialized: all pipes <15%, issue 46%).
// ---------------------------------------------------------------------------
__global__ void __launch_bounds__(256) pass1_kernel(const float* __restrict__ mask) {
    const int lane = threadIdx.x & 31;
    const int warp = threadIdx.x >> 5;
    const int row  = blockIdx.x * 8 + warp;     // b*H + y

    if (blockIdx.x == 0 && threadIdx.x == 0) g_maxbits = 0u;

    const float* mrow = mask + row * W;

    unsigned int w[8];
    #pragma unroll
    for (int j = 0; j < 8; j++) {
        const float v = mrow[32 * j + lane];    // 128B coalesced per ballot
        w[j] = __ballot_sync(0xFFFFFFFFu, v > 0.5f);
    }

    float* trow = g_tmp + row * W;
    #pragma unroll
    for (int j = 0; j < 8; j++) {
        const int x = 32 * j + lane;

        // nearest fg index <= x
        int L = -1;
        const unsigned int ml = w[j] & (0xFFFFFFFFu >> (31 - lane));
        if (ml) {
            L = 32 * j + 31 - __clz(ml);
        } else {
            #pragma unroll
            for (int k = 6; k >= 0; k--)
                if (L < 0 && k < j && w[k]) L = 32 * k + 31 - __clz(w[k]);
        }

        // nearest fg index >= x
        int R = W;
        const unsigned int mr = w[j] & (0xFFFFFFFFu << lane);
        if (mr) {
            R = 32 * j + __ffs(mr) - 1;
        } else {
            #pragma unroll
            for (int k = 1; k < 8; k++)
                if (R == W && k > j && w[k]) R = 32 * k + __ffs(w[k]) - 1;
        }

        float best = INF_VAL;                   // matches reference: xq==x gives INF+0
        if (L >= 0) { const int d = x - L; best = fminf(best, (float)(d * d)); }
        if (R < W)  { const int d = R - x; best = fminf(best, (float)(d * d)); }
        trow[x] = best;                          // 128B coalesced per j
    }
}

// ---------------------------------------------------------------------------
// Pass 2 (y-direction): d2[b,yi,x] = min_yq ( (yi-yq)^2 + tmp[b,yq,x] ).
// Same tiling as before; inner loop now uses packed fma.rn.f32x2 so each yq
// step costs 4 FMA2 + 8 FMNMX + 4 ADD2 + 1 LDS (~18 issue slots vs 26).
// Arithmetic is bit-identical (fused rn per 32-bit lane).
// ---------------------------------------------------------------------------
__global__ void __launch_bounds__(256) pass2_kernel(const float* __restrict__ tmp,
                                                    float* __restrict__ d2out) {
    const int b  = blockIdx.z;
    const int xt = blockIdx.x;            // 0..7  (x tile of 32)
    const int yc = blockIdx.y;            // 0..3  (yi chunk of 64)
    const int tx = threadIdx.x;           // 0..31
    const int ty = threadIdx.y;           // 0..7

    __shared__ float sh[H][32];

    const float* base = tmp + b * H * W + xt * 32;
    #pragma unroll
    for (int i = 0; i < H / 8; i++) {
        const int y = ty + i * 8;
        sh[y][tx] = base[y * W + tx];     // 128B coalesced per warp
    }
    __syncthreads();

    const int yi0 = yc * 64 + ty;         // thread's yi set: yi0 + 8k, k=0..7
    float best[8];
    unsigned long long dyp[4];            // packed (dy_{2i}, dy_{2i+1})
    #pragma unroll
    for (int i = 0; i < 4; i++) {
        best[2 * i]     = 3e38f;
        best[2 * i + 1] = 3e38f;
        dyp[i] = pack2((float)(yi0 + 16 * i), (float)(yi0 + 16 * i + 8));
    }
    const unsigned long long neg1 = pack2(-1.0f, -1.0f);

    #pragma unroll 4
    for (int yq = 0; yq < H; yq++) {
        const float s = sh[yq][tx];
        const unsigned long long s2 = pack2(s, s);
        #pragma unroll
        for (int i = 0; i < 4; i++) {
            float lo, hi;
            unpack2(fma2(dyp[i], dyp[i], s2), lo, hi);
            best[2 * i]     = fminf(best[2 * i],     lo);
            best[2 * i + 1] = fminf(best[2 * i + 1], hi);
            dyp[i] = add2(dyp[i], neg1);
        }
    }

    float lmax = 0.0f;
    float* out = d2out + b * H * W + xt * 32 + tx;
    #pragma unroll
    for (int k = 0; k < 8; k++) {
        const int yi = yi0 + 8 * k;
        out[yi * W] = best[k];
        lmax = fmaxf(lmax, best[k]);
    }

    #pragma unroll
    for (int off = 16; off; off >>= 1)
        lmax = fmaxf(lmax, __shfl_xor_sync(0xFFFFFFFFu, lmax, off));
    if (tx == 0)
        atomicMax(&g_maxbits, __float_as_uint(lmax));   // valid: all >= 0
}

// ---------------------------------------------------------------------------
// Finalize: out = 2 / (1 + exp(sqrt(d2) * 50 / (sqrt(max d2) + 1)))
// ---------------------------------------------------------------------------
__global__ void finalize_kernel(const float* __restrict__ d2,
                                float* __restrict__ out, int n) {
    const int i = blockIdx.x * blockDim.x + threadIdx.x;
    if (i >= n) return;
    const float maxd = sqrtf(__uint_as_float(g_maxbits)) + 1.0f;
    const float scale = 50.0f / maxd;
    const float z = sqrtf(d2[i]) * scale;
    out[i] = 2.0f / (1.0f + expf(z));
}

// ---------------------------------------------------------------------------
extern "C" void kernel_launch(void* const* d_in, const int* in_sizes, int n_in,
                              void* d_out, int out_size) {
    const float* mask = (const float*)d_in[0];
    float* out = (float*)d_out;

    float* tmp_ptr;
    float* d2_ptr;
    cudaGetSymbolAddress((void**)&tmp_ptr, g_tmp);
    cudaGetSymbolAddress((void**)&d2_ptr, g_d2);

    pass1_kernel<<<BATCH * H / 8, 256>>>(mask);
    {
        dim3 grid(W / 32, H / 64, BATCH);
        dim3 block(32, 8);
        pass2_kernel<<<grid, block>>>(tmp_ptr, d2_ptr);
    }
    finalize_kernel<<<(NTOT + 255) / 256, 256>>>(d2_ptr, out, NTOT);
}